// round 13
// baseline (speedup 1.0000x reference)
#include <cuda_runtime.h>
#include <math.h>
#include <stdint.h>

#define D_MODEL 1024
#define D_HID   256
#define N_EXP   64
#define NTOK    16384

// ---------------- packed fp32x2 helpers (FFMA2 path) ----------------
__device__ __forceinline__ unsigned long long pack2(float lo, float hi) {
    unsigned long long r;
    asm("mov.b64 %0, {%1, %2};" : "=l"(r) : "f"(lo), "f"(hi));
    return r;
}
__device__ __forceinline__ void ffma2(unsigned long long& d,
                                      unsigned long long a,
                                      unsigned long long b) {
    asm("fma.rn.f32x2 %0, %1, %2, %0;" : "+l"(d) : "l"(a), "l"(b));
}
__device__ __forceinline__ float2 unpack2(unsigned long long v) {
    float2 f;
    asm("mov.b64 {%0, %1}, %2;" : "=f"(f.x), "=f"(f.y) : "l"(v));
    return f;
}
__device__ __forceinline__ void cp16(uint32_t saddr, const void* gsrc) {
    asm volatile("cp.async.cg.shared.global [%0], [%1], 16;" :: "r"(saddr), "l"(gsrc) : "memory");
}
#define CP_COMMIT() asm volatile("cp.async.commit_group;" ::: "memory")
#define CP_WAIT0()  asm volatile("cp.async.wait_group 0;" ::: "memory")
#define CP_WAIT1()  asm volatile("cp.async.wait_group 1;" ::: "memory")

__device__ __forceinline__ uint32_t smem_u32(const void* p) {
    uint32_t a;
    asm("{ .reg .u64 t; cvta.to.shared.u64 t, %1; cvt.u32.u64 %0, t; }" : "=r"(a) : "l"(p));
    return a;
}

// =============================================================================
// Fully fused gating network, pure fp32 (exact), re-tiled for occupancy 3:
//   H = tanh(X@W1+b1) -> smem Ht[k][tok] ; logits = H@W2+b2 ;
//   top-2 softmax -> dense gates; outputs (gates, logits).
//
// CTA: 256 threads, M=32 tokens (grid 512), N=256, BK=16, occ 3.
// Thread tile: 8 consecutive tokens x 4 cols (acc = 16 f32x2).
//   warp wid -> col block wid*32; lane: tm=lane>>3 (8-token group),
//   tn=lane&7 (4-col group).
//
// Dynamic smem (bytes):
//   [0, 34816)       Ht[256][34]   (overlay after tail: Ls[32][68] @0)
//   [34816, 37120)   A buf0: As[16][36]
//   [37120, 39424)   A buf1
//   [39424, 56064)   B buf0: Bs[16][260]
//   [56064, 72704)   B buf1
// =============================================================================
#define SM_HT  0
#define SM_A0  34816
#define SM_A1  37120
#define SM_B0  39424
#define SM_B1  56064
#define SM_LS  0
#define SM_TOTAL 72704

__global__ __launch_bounds__(256, 3)
void fused_gating(const float* __restrict__ X,
                  const float* __restrict__ W1,
                  const float* __restrict__ b1,
                  const float* __restrict__ W2,
                  const float* __restrict__ b2,
                  float* __restrict__ out_gates,
                  float* __restrict__ out_logits) {
    extern __shared__ char sm[];
    __shared__ float b1s[256];
    __shared__ float b2s[64];
    __shared__ int   si1[32], si2[32];
    __shared__ float sg1[32], sg2[32];

    const uint32_t sb = smem_u32(sm);
    const int tid  = threadIdx.x;
    const int wid  = tid >> 5, lane = tid & 31;
    const int m0   = blockIdx.x * 32;
    const int wn   = wid;              // col block (32 cols)
    const int tm   = lane >> 3;        // 8-token group: tokens tm*8..tm*8+7
    const int tn   = lane & 7;         // 4-col group

    b1s[tid] = b1[tid];
    if (tid < 64) b2s[tid] = b2[tid];

    // X staging: 512 floats/chunk; thread: tok=tid>>3, k2=(tid&7)*2 (float2)
    const int xtok = tid >> 3;          // 0..31
    const int xk2  = (tid & 7) * 2;     // 0,2,..,14

    // acc[p][c] = f32x2 over tokens (tm*8+2p, +1), col wn*32+tn*4+c
    unsigned long long acc[4][4];
#pragma unroll
    for (int p = 0; p < 4; p++)
#pragma unroll
        for (int c = 0; c < 4; c++) acc[p][c] = 0ull;

    float2 xa;

    // ---- prologue: stage chunk 0 ----
    xa = *(const float2*)(X + (size_t)(m0 + xtok) * D_MODEL + xk2);
    {
        float* A = (float*)(sm + SM_A0);
        A[xk2 * 36 + xtok]       = xa.x;
        A[(xk2 + 1) * 36 + xtok] = xa.y;
    }
#pragma unroll
    for (int i = 0; i < 4; i++) {
        int q = tid + i * 256;
        int krow = q >> 6, c16 = q & 63;
        cp16(sb + SM_B0 + krow * 1040 + c16 * 16, W1 + (size_t)krow * D_HID + c16 * 4);
    }
    CP_COMMIT();

    // ---- mainloop: 64 chunks of K=16 ----
    for (int c = 0; c < 64; c++) {
        const int b = c & 1;
        if (c < 63) {
            const int kt = (c + 1) * 16;
            xa = *(const float2*)(X + (size_t)(m0 + xtok) * D_MODEL + kt + xk2);
            const uint32_t Bb = sb + (b ? SM_B0 : SM_B1);
#pragma unroll
            for (int i = 0; i < 4; i++) {
                int q = tid + i * 256;
                int krow = q >> 6, c16 = q & 63;
                cp16(Bb + krow * 1040 + c16 * 16,
                     W1 + (size_t)(kt + krow) * D_HID + c16 * 4);
            }
            CP_COMMIT();
            CP_WAIT1();
        } else {
            CP_WAIT0();
        }
        __syncthreads();

        const float* As = (const float*)(sm + (b ? SM_A1 : SM_A0));
        const float* Bs = (const float*)(sm + (b ? SM_B1 : SM_B0));

#pragma unroll
        for (int k = 0; k < 16; k++) {
            // A: 8 consecutive tokens as 4 f32x2 pairs (two 16B loads, no packs)
            ulonglong2 u0 = *(const ulonglong2*)(As + k * 36 + tm * 8);
            ulonglong2 u1 = *(const ulonglong2*)(As + k * 36 + tm * 8 + 4);
            // B: 4 consecutive cols, broadcast-packed
            float4 bv = *(const float4*)(Bs + k * 260 + wn * 32 + tn * 4);
            unsigned long long bb[4];
            bb[0] = pack2(bv.x, bv.x); bb[1] = pack2(bv.y, bv.y);
            bb[2] = pack2(bv.z, bv.z); bb[3] = pack2(bv.w, bv.w);
#pragma unroll
            for (int cc = 0; cc < 4; cc++) {
                ffma2(acc[0][cc], u0.x, bb[cc]);
                ffma2(acc[1][cc], u0.y, bb[cc]);
                ffma2(acc[2][cc], u1.x, bb[cc]);
                ffma2(acc[3][cc], u1.y, bb[cc]);
            }
        }
        __syncthreads();
        if (c < 63) {
            float* A = (float*)(sm + (b ? SM_A0 : SM_A1));
            A[xk2 * 36 + xtok]       = xa.x;
            A[(xk2 + 1) * 36 + xtok] = xa.y;
        }
    }

    // ---- H = tanh(acc + b1) -> Ht[k][tok] (transposed, stride 34) ----
    float* Ht = (float*)(sm + SM_HT);
#pragma unroll
    for (int p = 0; p < 4; p++) {
        int tok0 = tm * 8 + 2 * p;
#pragma unroll
        for (int cc = 0; cc < 4; cc++) {
            int col = wn * 32 + tn * 4 + cc;
            float2 v = unpack2(acc[p][cc]);
            float2 hv;
            hv.x = tanhf(v.x + b1s[col]);
            hv.y = tanhf(v.y + b1s[col]);
            *(float2*)(Ht + col * 34 + tok0) = hv;
        }
    }
    __syncthreads();

    // ---- tail GEMM2: logits = Ht^T @ W2 (W2 via __ldg, L2-hot) ----
    // thread: tp = tid>>4 (token pair 2tp,2tp+1), eg = tid&15 (experts 4eg..+3)
    const int tp = tid >> 4;
    const int eg = tid & 15;

    unsigned long long acc2[4];
    acc2[0] = acc2[1] = acc2[2] = acc2[3] = 0ull;

#pragma unroll 8
    for (int k = 0; k < D_HID; k++) {
        unsigned long long hh = *(const unsigned long long*)(Ht + k * 34 + 2 * tp);
        float4 wv = __ldg((const float4*)(W2 + (size_t)k * N_EXP + eg * 4));
        ffma2(acc2[0], hh, pack2(wv.x, wv.x));
        ffma2(acc2[1], hh, pack2(wv.y, wv.y));
        ffma2(acc2[2], hh, pack2(wv.z, wv.z));
        ffma2(acc2[3], hh, pack2(wv.w, wv.w));
    }
    __syncthreads();                    // all Ht reads done; overlay Ls

    // ---- stage logits (+b2) into Ls[32][68] ----
    float* Ls = (float*)(sm + SM_LS);
#pragma unroll
    for (int cc = 0; cc < 4; cc++) {
        int e = eg * 4 + cc;
        float2 v = unpack2(acc2[cc]);
        Ls[(2 * tp) * 68 + e]     = v.x + b2s[e];
        Ls[(2 * tp + 1) * 68 + e] = v.y + b2s[e];
    }
    __syncthreads();

    // ---- per-token top-2 + softmax-of-2 ----
    if (tid < 32) {
        const float* Lrow = Ls + tid * 68;
        float v1 = -INFINITY, v2 = -INFINITY;
        int i1 = 0, i2 = 0;
#pragma unroll
        for (int e = 0; e < N_EXP; e++) {
            float v = Lrow[e];
            if (v > v1)      { v2 = v1; i2 = i1; v1 = v; i1 = e; }
            else if (v > v2) { v2 = v; i2 = e; }
        }
        float e2  = __expf(v2 - v1);
        float inv = 1.0f / (1.0f + e2);
        si1[tid] = i1; si2[tid] = i2;
        sg1[tid] = inv; sg2[tid] = e2 * inv;
    }
    __syncthreads();

    // ---- coalesced writeback: logits + dense gates ----
#pragma unroll
    for (int i = 0; i < 2; i++) {
        int f = tid + i * 256;                // 0..511
        int row = f >> 4, c4 = (f & 15) * 4;
        float4 lv = *(const float4*)(Ls + row * 68 + c4);
        int i1 = si1[row], i2 = si2[row];
        float g1 = sg1[row], g2 = sg2[row];
        float4 gv;
        gv.x = (c4 + 0 == i1) ? g1 : ((c4 + 0 == i2) ? g2 : 0.0f);
        gv.y = (c4 + 1 == i1) ? g1 : ((c4 + 1 == i2) ? g2 : 0.0f);
        gv.z = (c4 + 2 == i1) ? g1 : ((c4 + 2 == i2) ? g2 : 0.0f);
        gv.w = (c4 + 3 == i1) ? g1 : ((c4 + 3 == i2) ? g2 : 0.0f);
        const size_t base = (size_t)(m0 + row) * N_EXP + c4;
        *(float4*)(out_logits + base) = lv;
        *(float4*)(out_gates  + base) = gv;
    }
}

// =============================================================================
extern "C" void kernel_launch(void* const* d_in, const int* in_sizes, int n_in,
                              void* d_out, int out_size) {
    const float* x  = (const float*)d_in[0];   // [4,4096,1024]
    const float* W1 = (const float*)d_in[1];   // [1024,256]
    const float* b1 = (const float*)d_in[2];   // [256]
    const float* W2 = (const float*)d_in[3];   // [256,64]
    const float* b2 = (const float*)d_in[4];   // [64]

    float* out        = (float*)d_out;
    float* out_gates  = out;
    float* out_logits = out + (size_t)out_size / 2;

    cudaFuncSetAttribute(fused_gating, cudaFuncAttributeMaxDynamicSharedMemorySize,
                         SM_TOTAL);
    fused_gating<<<NTOK / 32, 256, SM_TOTAL>>>(x, W1, b1, W2, b2,
                                               out_gates, out_logits);
}